// round 11
// baseline (speedup 1.0000x reference)
#include <cuda_runtime.h>
#include <cuda_fp16.h>
#include <mma.h>
#include <math.h>
#include <stdint.h>

using namespace nvcuda;

#define BS 2
#define SEQ 2048
#define DIM 768
#define NH 12
#define HD 64
#define WINDOW 64
#define ROPE_BASE 10000.0f

#define QT 64
#define KTW 192
#define LDQ 72
#define LDKV 72
#define LDS 200
#define LDP 200
#define LDO 72
#define ATTN_SMEM (QT*LDQ*2 + KTW*LDKV*2 + QT*LDS*4 + QT*LDP*2)

#define MROWS 4096
#define KDIM 768

// ---- GEMM tiling: CTA 128x128, 8 warps (4x2) of 32x64, BK=32 fp16, 3 stages
#define GBM 128
#define GBN 128
#define GBK 32
#define GSTG 3
#define LDT 40
#define TILE_HALFS (GBM * LDT)
#define STAGE_HALFS (2 * TILE_HALFS)
#define PIPE_SMEM (GSTG * STAGE_HALFS * 2)          // 61440
#define LDC 132                                      // epilogue staging stride (floats); 132*4=528B = 33*16 (16B-aligned for WMMA)
#define QKV_SMEM (GBM * LDC * 4)                     // 67584
#define NKT (KDIM / GBK)

#define MODE_QKV 0
#define MODE_OUT 1

// ---------------- scratch ----------------------------------------------------
__device__ __half g_q[BS * NH * SEQ * HD];
__device__ __half g_k[BS * NH * SEQ * HD];
__device__ __half g_v[BS * NH * SEQ * HD];
__device__ __half g_hs_h[MROWS * DIM];
__device__ __half g_w1t[3 * DIM * DIM];
__device__ __half g_wot[DIM * DIM];
__device__ __half g_att[MROWS * DIM];

// ---------------- cp.async helpers -----------------------------------------
__device__ __forceinline__ uint32_t smem_u32(const void* p) {
    uint32_t a;
    asm("{ .reg .u64 t; cvta.to.shared.u64 t, %1; cvt.u32.u64 %0, t; }" : "=r"(a) : "l"(p));
    return a;
}
__device__ __forceinline__ void cp_async16(uint32_t dst, const void* src) {
    asm volatile("cp.async.cg.shared.global [%0], [%1], 16;" :: "r"(dst), "l"(src));
}
#define CP_COMMIT() asm volatile("cp.async.commit_group;" ::: "memory")
#define CP_WAIT(n)  asm volatile("cp.async.wait_group %0;" :: "n"(n) : "memory")

// ---------------- fp16 mma GEMM: C[M,N] = A[M,768] @ Bt[N,768]^T -------------
// MODE_QKV: fused RoPE epilogue -> fp16 q/k/v in [b,h,s,d].
// MODE_OUT: plain fp32 C output.
template <int MODE>
__global__ __launch_bounds__(256, 2) void gemm_f16(
    const __half* __restrict__ A, const __half* __restrict__ Bt,
    float* __restrict__ C, int N,
    __half* __restrict__ qo, __half* __restrict__ ko, __half* __restrict__ vo)
{
    extern __shared__ __half sm[];
    const uint32_t sbase = smem_u32(sm);
    const int tid = threadIdx.x;
    const int warp = tid >> 5;
    const int wm = warp >> 1;               // 0..3
    const int wn = warp & 1;                // 0..1
    const long bm = (long)blockIdx.y * GBM;
    const long bn = (long)blockIdx.x * GBN;

    wmma::fragment<wmma::accumulator, 16, 16, 16, float> acc[2][4];
#pragma unroll
    for (int i = 0; i < 2; i++)
#pragma unroll
        for (int j = 0; j < 4; j++) wmma::fill_fragment(acc[i][j], 0.0f);

    // stage loader: 1024 x 16B chunks, 4 per thread
    auto load_stage = [&](int buf, int k0) {
        uint32_t stage_base = sbase + (uint32_t)(buf * STAGE_HALFS * 2);
#pragma unroll
        for (int it = 0; it < 4; it++) {
            int c = tid + it * 256;
            int mat = c >> 9;
            int row = (c >> 2) & 127;
            int ch  = c & 3;
            const __half* g = (mat ? (Bt + (bn + row) * KDIM) : (A + (bm + row) * KDIM))
                              + k0 + ch * 8;
            uint32_t dst = stage_base + (uint32_t)((mat * TILE_HALFS + row * LDT + ch * 8) * 2);
            cp_async16(dst, g);
        }
    };

    load_stage(0, 0);
    CP_COMMIT();
    load_stage(1, GBK);
    CP_COMMIT();

#pragma unroll 1
    for (int kt = 0; kt < NKT; kt++) {
        CP_WAIT(GSTG - 2);
        __syncthreads();

        int nxt = kt + GSTG - 1;
        if (nxt < NKT) load_stage(nxt % GSTG, nxt * GBK);
        CP_COMMIT();

        const __half* As = sm + (kt % GSTG) * STAGE_HALFS;
        const __half* Bs = As + TILE_HALFS;
#pragma unroll
        for (int kk = 0; kk < GBK; kk += 16) {
            wmma::fragment<wmma::matrix_a, 16, 16, 16, __half, wmma::row_major> af[2];
            wmma::fragment<wmma::matrix_b, 16, 16, 16, __half, wmma::col_major> bf[4];
#pragma unroll
            for (int i = 0; i < 2; i++)
                wmma::load_matrix_sync(af[i], As + (wm * 32 + i * 16) * LDT + kk, LDT);
#pragma unroll
            for (int j = 0; j < 4; j++)
                wmma::load_matrix_sync(bf[j], Bs + (wn * 64 + j * 16) * LDT + kk, LDT);
#pragma unroll
            for (int i = 0; i < 2; i++)
#pragma unroll
                for (int j = 0; j < 4; j++)
                    wmma::mma_sync(acc[i][j], af[i], bf[j], acc[i][j]);
        }
    }

    if (MODE == MODE_OUT) {
#pragma unroll
        for (int i = 0; i < 2; i++)
#pragma unroll
            for (int j = 0; j < 4; j++)
                wmma::store_matrix_sync(
                    C + (bm + wm * 32 + i * 16) * N + bn + wn * 64 + j * 16,
                    acc[i][j], N, wmma::mem_row_major);
        return;
    }

    // ---- MODE_QKV: stage accumulators, apply RoPE, emit fp16 q/k/v ----
    CP_WAIT(0);
    __syncthreads();                    // all warps done reading pipeline smem
    float* stg = (float*)sm;
#pragma unroll
    for (int i = 0; i < 2; i++)
#pragma unroll
        for (int j = 0; j < 4; j++)
            wmma::store_matrix_sync(stg + (wm * 32 + i * 16) * LDC + wn * 64 + j * 16,
                                    acc[i][j], LDC, wmma::mem_row_major);
    __syncthreads();

    {
        const int row = tid >> 1;            // 0..127
        const int hoff = (tid & 1) * 64;     // 64-col half = one (sel, head)
        const long mrow = bm + row;
        const int s = (int)(mrow & (SEQ - 1));
        const int b = (int)(mrow >> 11);
        const int coln = (int)bn + hoff;
        const int sel = coln / DIM;          // 0=q 1=k 2=v
        const int h = (coln % DIM) / HD;

        __half* dst = (sel == 0 ? qo : sel == 1 ? ko : vo)
                      + ((long)(b * NH + h) * SEQ + s) * HD;
        const float* src = stg + row * LDC + hoff;

        if (sel == 2) {
#pragma unroll
            for (int c = 0; c < 64; c += 2) {
                __half2 hv = __floats2half2_rn(src[c], src[c + 1]);
                *(__half2*)(dst + c) = hv;
            }
        } else {
            const float lb = logf(ROPE_BASE);
#pragma unroll
            for (int fi = 0; fi < 32; fi += 2) {
                float x1a = src[fi],      x1b = src[fi + 1];
                float x2a = src[fi + 32], x2b = src[fi + 33];
                float if0 = expf(-(2.0f * (float)fi / (float)HD) * lb);
                float if1 = expf(-(2.0f * (float)(fi + 1) / (float)HD) * lb);
                float sn0, cs0, sn1, cs1;
                sincosf((float)s * if0, &sn0, &cs0);
                sincosf((float)s * if1, &sn1, &cs1);
                __half2 lo = __floats2half2_rn(x1a * cs0 - x2a * sn0,
                                               x1b * cs1 - x2b * sn1);
                __half2 hi = __floats2half2_rn(x2a * cs0 + x1a * sn0,
                                               x2b * cs1 + x1b * sn1);
                *(__half2*)(dst + fi) = lo;
                *(__half2*)(dst + fi + 32) = hi;
            }
        }
    }
}

// ---------------- fp32 -> fp16 conversion -----------------------------------
__global__ void to_half(const float4* __restrict__ src, uint2* __restrict__ dst, int n4)
{
    int i = blockIdx.x * blockDim.x + threadIdx.x;
    if (i >= n4) return;
    float4 x = src[i];
    __half2 a = __floats2half2_rn(x.x, x.y);
    __half2 b = __floats2half2_rn(x.z, x.w);
    dst[i] = make_uint2(*(uint32_t*)&a, *(uint32_t*)&b);
}

__global__ void transpose_half(const float* __restrict__ src, __half* __restrict__ dst,
                               int Kd, int Nd)
{
    __shared__ float t[32][33];
    int n0 = blockIdx.x * 32, k0 = blockIdx.y * 32;
    int tx = threadIdx.x, ty = threadIdx.y;
#pragma unroll
    for (int r = 0; r < 4; r++)
        t[ty + r * 8][tx] = src[(size_t)(k0 + ty + r * 8) * Nd + n0 + tx];
    __syncthreads();
#pragma unroll
    for (int r = 0; r < 4; r++)
        dst[(size_t)(n0 + ty + r * 8) * Kd + k0 + tx] = __float2half_rn(t[tx][ty + r * 8]);
}

// ---------------- sliding-window attention (fp16 WMMA, fp32 softmax) --------
__global__ __launch_bounds__(256) void attn_kernel(
    const __half* __restrict__ q, const __half* __restrict__ k,
    const __half* __restrict__ v, __half* __restrict__ o)
{
    extern __shared__ char smraw[];
    __half* Qs  = (__half*)smraw;
    __half* KVs = Qs + QT * LDQ;
    float*  Ss  = (float*)(KVs + KTW * LDKV);
    __half* Ps  = (__half*)(Ss + QT * LDS);

    const int qt = blockIdx.x;
    const int h  = blockIdx.y;
    const int b  = blockIdx.z;
    const int i0 = qt * QT;
    const int j0 = i0 - WINDOW;
    const int tid = threadIdx.x;
    const int warp = tid >> 5;
    const int lane = tid & 31;

    const __half* Qg = q + ((long)(b * NH + h) * SEQ) * HD;
    const __half* Kg = k + ((long)(b * NH + h) * SEQ) * HD;
    const __half* Vg = v + ((long)(b * NH + h) * SEQ) * HD;

    for (int f = tid; f < QT * 8; f += 256) {
        int row = f >> 3, c8 = f & 7;
        uint4 val = *(const uint4*)(Qg + (long)(i0 + row) * HD + c8 * 8);
        *(uint4*)(Qs + row * LDQ + c8 * 8) = val;
    }
    for (int f = tid; f < KTW * 8; f += 256) {
        int row = f >> 3, c8 = f & 7;
        int j = j0 + row;
        uint4 val = make_uint4(0u, 0u, 0u, 0u);
        if (j >= 0 && j < SEQ) val = *(const uint4*)(Kg + (long)j * HD + c8 * 8);
        *(uint4*)(KVs + row * LDKV + c8 * 8) = val;
    }
    __syncthreads();

    // ---- S = Q @ K^T ----
    {
        const int wr = (warp & 3) * 16;
        const int wc = (warp >> 2) * 96;
        wmma::fragment<wmma::matrix_a, 16, 16, 16, __half, wmma::row_major> af[4];
#pragma unroll
        for (int kk = 0; kk < 4; kk++)
            wmma::load_matrix_sync(af[kk], Qs + wr * LDQ + kk * 16, LDQ);
#pragma unroll
        for (int jt = 0; jt < 6; jt++) {
            wmma::fragment<wmma::accumulator, 16, 16, 16, float> acc;
            wmma::fill_fragment(acc, 0.0f);
#pragma unroll
            for (int kk = 0; kk < 4; kk++) {
                wmma::fragment<wmma::matrix_b, 16, 16, 16, __half, wmma::col_major> bf;
                wmma::load_matrix_sync(bf, KVs + (wc + jt * 16) * LDKV + kk * 16, LDKV);
                wmma::mma_sync(acc, af[kk], bf, acc);
            }
            wmma::store_matrix_sync(Ss + wr * LDS + wc + jt * 16, acc, LDS, wmma::mem_row_major);
        }
    }
    __syncthreads();

    // ---- load V window ----
    for (int f = tid; f < KTW * 8; f += 256) {
        int row = f >> 3, c8 = f & 7;
        int j = j0 + row;
        uint4 val = make_uint4(0u, 0u, 0u, 0u);
        if (j >= 0 && j < SEQ) val = *(const uint4*)(Vg + (long)j * HD + c8 * 8);
        *(uint4*)(KVs + row * LDKV + c8 * 8) = val;
    }

    // ---- softmax ----
    {
        const float scale = 0.125f;
#pragma unroll
        for (int rr = 0; rr < 8; rr++) {
            int r = warp * 8 + rr;
            float e[6];
            float m = -INFINITY;
#pragma unroll
            for (int t = 0; t < 6; t++) {
                int c = lane + 32 * t;
                int jg = j0 + c;
                bool valid = (c >= r) && (c <= r + 2 * WINDOW) && (jg >= 0) && (jg < SEQ);
                float s = valid ? Ss[r * LDS + c] * scale : -INFINITY;
                e[t] = s;
                m = fmaxf(m, s);
            }
#pragma unroll
            for (int off = 16; off > 0; off >>= 1)
                m = fmaxf(m, __shfl_xor_sync(0xffffffffu, m, off));
            float sum = 0.0f;
#pragma unroll
            for (int t = 0; t < 6; t++) {
                e[t] = __expf(e[t] - m);
                sum += e[t];
            }
#pragma unroll
            for (int off = 16; off > 0; off >>= 1)
                sum += __shfl_xor_sync(0xffffffffu, sum, off);
            float inv = 1.0f / sum;
#pragma unroll
            for (int t = 0; t < 6; t++)
                Ps[r * LDP + lane + 32 * t] = __float2half_rn(e[t] * inv);
        }
    }
    __syncthreads();

    // ---- O = P @ V ----
    {
        const int wr = (warp & 3) * 16;
        const int wc = (warp >> 2) * 32;
        wmma::fragment<wmma::accumulator, 16, 16, 16, float> acc[2];
        wmma::fill_fragment(acc[0], 0.0f);
        wmma::fill_fragment(acc[1], 0.0f);
#pragma unroll
        for (int kk = 0; kk < 12; kk++) {
            wmma::fragment<wmma::matrix_a, 16, 16, 16, __half, wmma::row_major> af;
            wmma::load_matrix_sync(af, Ps + wr * LDP + kk * 16, LDP);
#pragma unroll
            for (int t = 0; t < 2; t++) {
                wmma::fragment<wmma::matrix_b, 16, 16, 16, __half, wmma::row_major> bf;
                wmma::load_matrix_sync(bf, KVs + kk * 16 * LDKV + wc + t * 16, LDKV);
                wmma::mma_sync(acc[t], af, bf, acc[t]);
            }
        }
#pragma unroll
        for (int t = 0; t < 2; t++)
            wmma::store_matrix_sync(Ss + wr * LDO + wc + t * 16, acc[t], LDO, wmma::mem_row_major);
    }
    __syncthreads();

    for (int idx = tid; idx < QT * 16; idx += 256) {
        int row = idx >> 4;
        int c4  = (idx & 15) * 4;
        const float* src = Ss + row * LDO + c4;
        __half2 h01 = __floats2half2_rn(src[0], src[1]);
        __half2 h23 = __floats2half2_rn(src[2], src[3]);
        long orow = ((long)(b * SEQ + i0 + row)) * DIM + h * HD + c4;
        *(uint2*)(o + orow) = make_uint2(*(uint32_t*)&h01, *(uint32_t*)&h23);
    }
}

// ---------------------------------------------------------------------------
extern "C" void kernel_launch(void* const* d_in, const int* in_sizes, int n_in,
                              void* d_out, int out_size)
{
    const float* hs   = (const float*)d_in[0];
    const float* Wqkv = (const float*)d_in[1];
    const float* Wo   = (const float*)d_in[2];
    float* out = (float*)d_out;

    __half *q, *k, *v, *hs_h, *w1t, *wot, *att;
    cudaGetSymbolAddress((void**)&q,    g_q);
    cudaGetSymbolAddress((void**)&k,    g_k);
    cudaGetSymbolAddress((void**)&v,    g_v);
    cudaGetSymbolAddress((void**)&hs_h, g_hs_h);
    cudaGetSymbolAddress((void**)&w1t,  g_w1t);
    cudaGetSymbolAddress((void**)&wot,  g_wot);
    cudaGetSymbolAddress((void**)&att,  g_att);

    cudaFuncSetAttribute(gemm_f16<MODE_QKV>, cudaFuncAttributeMaxDynamicSharedMemorySize, QKV_SMEM);
    cudaFuncSetAttribute(gemm_f16<MODE_OUT>, cudaFuncAttributeMaxDynamicSharedMemorySize, PIPE_SMEM);
    cudaFuncSetAttribute(attn_kernel, cudaFuncAttributeMaxDynamicSharedMemorySize, ATTN_SMEM);

    // 0) convert inputs to fp16
    {
        int n4 = MROWS * DIM / 4;
        to_half<<<(n4 + 255) / 256, 256>>>((const float4*)hs, (uint2*)hs_h, n4);
        transpose_half<<<dim3(3 * DIM / 32, DIM / 32), dim3(32, 8)>>>(Wqkv, w1t, DIM, 3 * DIM);
        transpose_half<<<dim3(DIM / 32, DIM / 32), dim3(32, 8)>>>(Wo, wot, DIM, DIM);
    }

    // 1) QKV projection + fused RoPE -> fp16 q/k/v [b,h,s,d]
    gemm_f16<MODE_QKV><<<dim3(3 * DIM / GBN, MROWS / GBM), 256, QKV_SMEM>>>(
        hs_h, w1t, nullptr, 3 * DIM, q, k, v);

    // 2) sliding-window attention
    {
        dim3 grid(SEQ / QT, NH, BS);
        attn_kernel<<<grid, 256, ATTN_SMEM>>>(q, k, v, att);
    }

    // 3) output projection
    gemm_f16<MODE_OUT><<<dim3(DIM / GBN, MROWS / GBM), 256, PIPE_SMEM>>>(
        att, wot, out, DIM, nullptr, nullptr, nullptr);
}